// round 5
// baseline (speedup 1.0000x reference)
#include <cuda_runtime.h>
#include <math_constants.h>
#include <cstdint>

#define BATCH 32
#define SEQ   2048
#define CDIM  384
#define HDIM  64
#define M_TOT (BATCH*SEQ)

// scratch: q (pre-scaled, tf32-rounded), k, v — [B*T, H] row-major
__device__ __align__(16) float g_k[M_TOT*HDIM];
__device__ __align__(16) float g_q[M_TOT*HDIM];
__device__ __align__(16) float g_v[M_TOT*HDIM];

__device__ __forceinline__ float f2tf(float f) {
    uint32_t r;
    asm("cvt.rna.tf32.f32 %0, %1;" : "=r"(r) : "f"(f));
    return __uint_as_float(r);
}

// D += A@B, m16n8k8 tf32, A row-major, B col-major
__device__ __forceinline__ void mma8(float* d, const uint32_t* a, uint32_t b0, uint32_t b1) {
    asm volatile("mma.sync.aligned.m16n8k8.row.col.f32.tf32.tf32.f32 "
        "{%0,%1,%2,%3}, {%4,%5,%6,%7}, {%8,%9}, {%0,%1,%2,%3};"
        : "+f"(d[0]), "+f"(d[1]), "+f"(d[2]), "+f"(d[3])
        : "r"(a[0]), "r"(a[1]), "r"(a[2]), "r"(a[3]), "r"(b0), "r"(b1));
}

// ---------------------------------------------------------------------------
// Projection: k/q/v = x @ W{k,q,v}.  M=65536, K=384, N=64, tf32 mma.
// M-tile 128, 256 threads / 8 warps. Warp w: rows 16w..16w+15, all 64 cols
// (8 n8 tiles) per weight.  Halves per-block weight L2 traffic vs M-tile 64.
// ---------------------------------------------------------------------------
#define PROJ_SMEM ((128*36 + 3*32*72) * (int)sizeof(float))

__global__ __launch_bounds__(256, 2) void proj_kernel(
    const float* __restrict__ x, const float* __restrict__ Wk,
    const float* __restrict__ Wq, const float* __restrict__ Wv)
{
    extern __shared__ __align__(16) float psm[];
    float* xs = psm;                   // [r][c] stride 36
    float* ws = psm + 128 * 36;        // [ww][kc][col] stride 72

    const int tid  = threadIdx.x;
    const int lane = tid & 31;
    const int w    = tid >> 5;
    const int row0 = blockIdx.x * 128;

    float acc[3][8][4];                // [weight][n8-tile][frag]
#pragma unroll
    for (int a = 0; a < 3; a++)
#pragma unroll
        for (int b = 0; b < 8; b++)
#pragma unroll
            for (int c = 0; c < 4; c++) acc[a][b][c] = 0.f;

    for (int c0 = 0; c0 < CDIM; c0 += 32) {
        __syncthreads();
        // x tile 128x32 -> tf32 -> smem
#pragma unroll
        for (int t = 0; t < 4; t++) {
            int fidx = tid + t * 256;            // 0..1023
            int r = fidx >> 3, c4 = (fidx & 7) * 4;
            float4 v = *(const float4*)&x[(size_t)(row0 + r) * CDIM + c0 + c4];
            v.x = f2tf(v.x); v.y = f2tf(v.y); v.z = f2tf(v.z); v.w = f2tf(v.w);
            *(float4*)&xs[r * 36 + c4] = v;
        }
        // W tiles 32x64 x3 -> tf32 -> smem
#pragma unroll
        for (int ww = 0; ww < 3; ww++)
#pragma unroll
            for (int t = 0; t < 2; t++) {
                int fidx = tid + t * 256;        // 0..511
                int kc = fidx >> 4, col4 = (fidx & 15) * 4;
                const float* W = (ww == 0) ? Wk : (ww == 1) ? Wq : Wv;
                float4 v = *(const float4*)&W[(c0 + kc) * HDIM + col4];
                v.x = f2tf(v.x); v.y = f2tf(v.y); v.z = f2tf(v.z); v.w = f2tf(v.w);
                *(float4*)&ws[ww * 32 * 72 + kc * 72 + col4] = v;
            }
        __syncthreads();

#pragma unroll
        for (int kt = 0; kt < 4; kt++) {
            uint32_t a[4];
            {
                int r = w * 16 + (lane >> 2);
                int c = kt * 8 + (lane & 3);
                a[0] = __float_as_uint(xs[r * 36 + c]);
                a[1] = __float_as_uint(xs[(r + 8) * 36 + c]);
                a[2] = __float_as_uint(xs[r * 36 + c + 4]);
                a[3] = __float_as_uint(xs[(r + 8) * 36 + c + 4]);
            }
            int kr = kt * 8 + (lane & 3);
#pragma unroll
            for (int ww = 0; ww < 3; ww++)
#pragma unroll
                for (int ntl = 0; ntl < 8; ntl++) {
                    int n0 = ntl * 8 + (lane >> 2);
                    uint32_t b0 = __float_as_uint(ws[ww * 32 * 72 + kr * 72 + n0]);
                    uint32_t b1 = __float_as_uint(ws[ww * 32 * 72 + (kr + 4) * 72 + n0]);
                    mma8(acc[ww][ntl], a, b0, b1);
                }
        }
    }

    // epilogue: round to tf32, coalesced f2 stores (q scaled by 0.125)
#pragma unroll
    for (int ntl = 0; ntl < 8; ntl++) {
        int rg = row0 + w * 16 + (lane >> 2);
        int cg = ntl * 8 + 2 * (lane & 3);
        size_t o0 = (size_t)rg * HDIM + cg;
        size_t o1 = (size_t)(rg + 8) * HDIM + cg;
        const float* ak = acc[0][ntl];
        const float* aq = acc[1][ntl];
        const float* av = acc[2][ntl];
        *(float2*)&g_k[o0] = make_float2(f2tf(ak[0]), f2tf(ak[1]));
        *(float2*)&g_k[o1] = make_float2(f2tf(ak[2]), f2tf(ak[3]));
        *(float2*)&g_q[o0] = make_float2(f2tf(aq[0] * 0.125f), f2tf(aq[1] * 0.125f));
        *(float2*)&g_q[o1] = make_float2(f2tf(aq[2] * 0.125f), f2tf(aq[3] * 0.125f));
        *(float2*)&g_v[o0] = make_float2(f2tf(av[0]), f2tf(av[1]));
        *(float2*)&g_v[o1] = make_float2(f2tf(av[2]), f2tf(av[3]));
    }
}

// ---------------------------------------------------------------------------
// Flash attention (causal), tf32 mma. Q-tile 64, K-tile 64, 4 warps.
// (verbatim from the 277us/188us round-3 version)
// ---------------------------------------------------------------------------
#define ATT_SMEM ((64*68 + 64*68 + 64*72) * (int)sizeof(float))

__global__ __launch_bounds__(128) void attn_kernel(float* __restrict__ out)
{
    extern __shared__ __align__(16) float sm[];
    float* qs = sm;                  // stride 68; later reused as ps
    float* ks = sm + 64 * 68;        // stride 68
    float* vs = sm + 2 * 64 * 68;    // stride 72

    const int tid  = threadIdx.x;
    const int lane = tid & 31;
    const int w    = tid >> 5;
    const int qt   = (gridDim.x - 1) - blockIdx.x;   // heavy tiles first
    const int b    = blockIdx.y;
    const int qrow0 = qt * 64;
    const size_t base = (size_t)b * SEQ * HDIM;

    // load q tile 64x64 (already tf32-rounded)
#pragma unroll
    for (int t = 0; t < 8; t++) {
        int fidx = tid + t * 128;            // 0..1023
        int r = fidx >> 4, h4 = (fidx & 15) * 4;
        *(float4*)&qs[r * 68 + h4] =
            *(const float4*)&g_q[base + (size_t)(qrow0 + r) * HDIM + h4];
    }
    __syncthreads();

    // preload q fragments (A-operand) for all 8 k-steps
    uint32_t qa[8][4];
    {
        int r = w * 16 + (lane >> 2);
#pragma unroll
        for (int kt8 = 0; kt8 < 8; kt8++) {
            int c = kt8 * 8 + (lane & 3);
            qa[kt8][0] = __float_as_uint(qs[r * 68 + c]);
            qa[kt8][1] = __float_as_uint(qs[(r + 8) * 68 + c]);
            qa[kt8][2] = __float_as_uint(qs[r * 68 + c + 4]);
            qa[kt8][3] = __float_as_uint(qs[(r + 8) * 68 + c + 4]);
        }
    }
    // qs rows 16w..16w+15 now warp-private -> reuse as ps (no block sync needed)
    float* ps = qs + w * 16 * 68;

    float o[8][4];
#pragma unroll
    for (int nt = 0; nt < 8; nt++)
#pragma unroll
        for (int e = 0; e < 4; e++) o[nt][e] = 0.f;
    float m0 = -CUDART_INF_F, m1 = -CUDART_INF_F, l0 = 0.f, l1 = 0.f;

    for (int kt = 0; kt <= qt; kt++) {
        __syncthreads();   // all warps done reading ks/vs from previous iter
#pragma unroll
        for (int t = 0; t < 8; t++) {
            int fidx = tid + t * 128;
            int r = fidx >> 4, h4 = (fidx & 15) * 4;
            *(float4*)&ks[r * 68 + h4] =
                *(const float4*)&g_k[base + (size_t)(kt * 64 + r) * HDIM + h4];
            *(float4*)&vs[r * 72 + h4] =
                *(const float4*)&g_v[base + (size_t)(kt * 64 + r) * HDIM + h4];
        }
        __syncthreads();

        // GEMM1: S = q @ k^T
        float s[8][4];
#pragma unroll
        for (int nt = 0; nt < 8; nt++)
#pragma unroll
            for (int e = 0; e < 4; e++) s[nt][e] = 0.f;

#pragma unroll
        for (int kt8 = 0; kt8 < 8; kt8++) {
            int hc = kt8 * 8 + (lane & 3);
#pragma unroll
            for (int nt = 0; nt < 8; nt++) {
                int sr = nt * 8 + (lane >> 2);
                uint32_t b0 = __float_as_uint(ks[sr * 68 + hc]);
                uint32_t b1 = __float_as_uint(ks[sr * 68 + hc + 4]);
                mma8(s[nt], qa[kt8], b0, b1);
            }
        }

        // causal mask on diagonal tile
        if (kt == qt) {
            int rg = 16 * w + (lane >> 2);
            int c0 = 2 * (lane & 3);
#pragma unroll
            for (int nt = 0; nt < 8; nt++) {
                int cg = c0 + 8 * nt;
                if (cg     > rg)     s[nt][0] = -CUDART_INF_F;
                if (cg + 1 > rg)     s[nt][1] = -CUDART_INF_F;
                if (cg     > rg + 8) s[nt][2] = -CUDART_INF_F;
                if (cg + 1 > rg + 8) s[nt][3] = -CUDART_INF_F;
            }
        }

        // online softmax (two rows per thread; reduce over 4-lane quads)
        float mx0 = -CUDART_INF_F, mx1 = -CUDART_INF_F;
#pragma unroll
        for (int nt = 0; nt < 8; nt++) {
            mx0 = fmaxf(mx0, fmaxf(s[nt][0], s[nt][1]));
            mx1 = fmaxf(mx1, fmaxf(s[nt][2], s[nt][3]));
        }
        mx0 = fmaxf(mx0, __shfl_xor_sync(0xffffffffu, mx0, 1, 4));
        mx0 = fmaxf(mx0, __shfl_xor_sync(0xffffffffu, mx0, 2, 4));
        mx1 = fmaxf(mx1, __shfl_xor_sync(0xffffffffu, mx1, 1, 4));
        mx1 = fmaxf(mx1, __shfl_xor_sync(0xffffffffu, mx1, 2, 4));

        float nm0 = fmaxf(m0, mx0), nm1 = fmaxf(m1, mx1);
        float al0 = __expf(m0 - nm0), al1 = __expf(m1 - nm1);
        m0 = nm0; m1 = nm1;

        float sum0 = 0.f, sum1 = 0.f;
#pragma unroll
        for (int nt = 0; nt < 8; nt++) {
            s[nt][0] = __expf(s[nt][0] - nm0); sum0 += s[nt][0];
            s[nt][1] = __expf(s[nt][1] - nm0); sum0 += s[nt][1];
            s[nt][2] = __expf(s[nt][2] - nm1); sum1 += s[nt][2];
            s[nt][3] = __expf(s[nt][3] - nm1); sum1 += s[nt][3];
        }
        sum0 += __shfl_xor_sync(0xffffffffu, sum0, 1, 4);
        sum0 += __shfl_xor_sync(0xffffffffu, sum0, 2, 4);
        sum1 += __shfl_xor_sync(0xffffffffu, sum1, 1, 4);
        sum1 += __shfl_xor_sync(0xffffffffu, sum1, 2, 4);
        l0 = l0 * al0 + sum0;
        l1 = l1 * al1 + sum1;
#pragma unroll
        for (int nt = 0; nt < 8; nt++) {
            o[nt][0] *= al0; o[nt][1] *= al0;
            o[nt][2] *= al1; o[nt][3] *= al1;
        }

        // store P (tf32-rounded) to warp-private smem
        {
            int r = lane >> 2;
#pragma unroll
            for (int nt = 0; nt < 8; nt++) {
                int c = nt * 8 + 2 * (lane & 3);
                *(float2*)&ps[r * 68 + c] = make_float2(f2tf(s[nt][0]), f2tf(s[nt][1]));
                *(float2*)&ps[(r + 8) * 68 + c] = make_float2(f2tf(s[nt][2]), f2tf(s[nt][3]));
            }
        }
        __syncwarp();

        // GEMM2: O += P @ V
#pragma unroll
        for (int st = 0; st < 8; st++) {
            uint32_t pa[4];
            int r = lane >> 2, c = st * 8 + (lane & 3);
            pa[0] = __float_as_uint(ps[r * 68 + c]);
            pa[1] = __float_as_uint(ps[(r + 8) * 68 + c]);
            pa[2] = __float_as_uint(ps[r * 68 + c + 4]);
            pa[3] = __float_as_uint(ps[(r + 8) * 68 + c + 4]);
            int vr = st * 8 + (lane & 3);
#pragma unroll
            for (int nt = 0; nt < 8; nt++) {
                int hc = nt * 8 + (lane >> 2);
                uint32_t b0 = __float_as_uint(vs[vr * 72 + hc]);
                uint32_t b1 = __float_as_uint(vs[(vr + 4) * 72 + hc]);
                mma8(o[nt], pa, b0, b1);
            }
        }
    }

    // epilogue
    float i0 = 1.f / l0, i1 = 1.f / l1;
    int rg = qrow0 + 16 * w + (lane >> 2);
#pragma unroll
    for (int nt = 0; nt < 8; nt++) {
        int cg = nt * 8 + 2 * (lane & 3);
        *(float2*)&out[base + (size_t)rg * HDIM + cg] =
            make_float2(o[nt][0] * i0, o[nt][1] * i0);
        *(float2*)&out[base + (size_t)(rg + 8) * HDIM + cg] =
            make_float2(o[nt][2] * i1, o[nt][3] * i1);
    }
}

// ---------------------------------------------------------------------------
extern "C" void kernel_launch(void* const* d_in, const int* in_sizes, int n_in,
                              void* d_out, int out_size)
{
    const float* x  = (const float*)d_in[0];
    const float* Wk = (const float*)d_in[1];
    const float* Wq = (const float*)d_in[2];
    const float* Wv = (const float*)d_in[3];
    float* out = (float*)d_out;

    cudaFuncSetAttribute(proj_kernel, cudaFuncAttributeMaxDynamicSharedMemorySize,
                         PROJ_SMEM);
    proj_kernel<<<M_TOT / 128, 256, PROJ_SMEM>>>(x, Wk, Wq, Wv);

    cudaFuncSetAttribute(attn_kernel, cudaFuncAttributeMaxDynamicSharedMemorySize,
                         ATT_SMEM);
    dim3 grid(SEQ / 64, BATCH);
    attn_kernel<<<grid, 128, ATT_SMEM>>>(out);
}

// round 6
// speedup vs baseline: 1.2680x; 1.2680x over previous
#include <cuda_runtime.h>
#include <math_constants.h>
#include <cstdint>

#define BATCH 32
#define SEQ   2048
#define CDIM  384
#define HDIM  64
#define M_TOT (BATCH*SEQ)

// scratch: q (pre-scaled, tf32-rounded), k, v — [B*T, H] row-major
__device__ __align__(16) float g_k[M_TOT*HDIM];
__device__ __align__(16) float g_q[M_TOT*HDIM];
__device__ __align__(16) float g_v[M_TOT*HDIM];

__device__ __forceinline__ float f2tf(float f) {
    uint32_t r;
    asm("cvt.rna.tf32.f32 %0, %1;" : "=r"(r) : "f"(f));
    return __uint_as_float(r);
}

// D += A@B, m16n8k8 tf32, A row-major, B col-major
__device__ __forceinline__ void mma8(float* d, const uint32_t* a, uint32_t b0, uint32_t b1) {
    asm volatile("mma.sync.aligned.m16n8k8.row.col.f32.tf32.tf32.f32 "
        "{%0,%1,%2,%3}, {%4,%5,%6,%7}, {%8,%9}, {%0,%1,%2,%3};"
        : "+f"(d[0]), "+f"(d[1]), "+f"(d[2]), "+f"(d[3])
        : "r"(a[0]), "r"(a[1]), "r"(a[2]), "r"(a[3]), "r"(b0), "r"(b1));
}

// ---------------------------------------------------------------------------
// Projection (verbatim from the 89us round-2/3 version).
// M=65536, K=384, N=64, tf32 mma. 128 threads / 4 warps, M-tile 64.
// ---------------------------------------------------------------------------
__global__ __launch_bounds__(128) void proj_kernel(
    const float* __restrict__ x, const float* __restrict__ Wk,
    const float* __restrict__ Wq, const float* __restrict__ Wv)
{
    __shared__ __align__(16) float xs[64 * 36];      // [r][c] stride 36
    __shared__ __align__(16) float ws[3][32 * 72];   // [kc][col] stride 72

    const int tid  = threadIdx.x;
    const int lane = tid & 31;
    const int w    = tid >> 5;
    const int row0 = blockIdx.x * 64;

    float acc[3][4][2][4];
#pragma unroll
    for (int a = 0; a < 3; a++)
#pragma unroll
        for (int b = 0; b < 4; b++)
#pragma unroll
            for (int c = 0; c < 2; c++)
#pragma unroll
                for (int d = 0; d < 4; d++) acc[a][b][c][d] = 0.f;

    for (int c0 = 0; c0 < CDIM; c0 += 32) {
        __syncthreads();
#pragma unroll
        for (int t = 0; t < 4; t++) {
            int fidx = tid + t * 128;
            int r = fidx >> 3, c4 = (fidx & 7) * 4;
            float4 v = *(const float4*)&x[(size_t)(row0 + r) * CDIM + c0 + c4];
            v.x = f2tf(v.x); v.y = f2tf(v.y); v.z = f2tf(v.z); v.w = f2tf(v.w);
            *(float4*)&xs[r * 36 + c4] = v;
        }
#pragma unroll
        for (int ww = 0; ww < 3; ww++) {
            const float* W = (ww == 0) ? Wk : (ww == 1) ? Wq : Wv;
#pragma unroll
            for (int t = 0; t < 4; t++) {
                int fidx = tid + t * 128;
                int kc = fidx >> 4, col4 = (fidx & 15) * 4;
                float4 v = *(const float4*)&W[(c0 + kc) * HDIM + col4];
                v.x = f2tf(v.x); v.y = f2tf(v.y); v.z = f2tf(v.z); v.w = f2tf(v.w);
                *(float4*)&ws[ww][kc * 72 + col4] = v;
            }
        }
        __syncthreads();

#pragma unroll
        for (int kt = 0; kt < 4; kt++) {
            uint32_t a[4][4];
#pragma unroll
            for (int mt = 0; mt < 4; mt++) {
                int r = mt * 16 + (lane >> 2);
                int c = kt * 8 + (lane & 3);
                a[mt][0] = __float_as_uint(xs[r * 36 + c]);
                a[mt][1] = __float_as_uint(xs[(r + 8) * 36 + c]);
                a[mt][2] = __float_as_uint(xs[r * 36 + c + 4]);
                a[mt][3] = __float_as_uint(xs[(r + 8) * 36 + c + 4]);
            }
            int kr = kt * 8 + (lane & 3);
#pragma unroll
            for (int ww = 0; ww < 3; ww++)
#pragma unroll
                for (int ntl = 0; ntl < 2; ntl++) {
                    int n0 = (w * 2 + ntl) * 8 + (lane >> 2);
                    uint32_t b0 = __float_as_uint(ws[ww][kr * 72 + n0]);
                    uint32_t b1 = __float_as_uint(ws[ww][(kr + 4) * 72 + n0]);
#pragma unroll
                    for (int mt = 0; mt < 4; mt++)
                        mma8(acc[ww][mt][ntl], a[mt], b0, b1);
                }
        }
    }

#pragma unroll
    for (int mt = 0; mt < 4; mt++)
#pragma unroll
        for (int ntl = 0; ntl < 2; ntl++) {
            int rg = row0 + mt * 16 + (lane >> 2);
            int cg = (w * 2 + ntl) * 8 + 2 * (lane & 3);
            size_t o0 = (size_t)rg * HDIM + cg;
            size_t o1 = (size_t)(rg + 8) * HDIM + cg;
            const float* ak = acc[0][mt][ntl];
            const float* aq = acc[1][mt][ntl];
            const float* av = acc[2][mt][ntl];
            *(float2*)&g_k[o0] = make_float2(f2tf(ak[0]), f2tf(ak[1]));
            *(float2*)&g_k[o1] = make_float2(f2tf(ak[2]), f2tf(ak[3]));
            *(float2*)&g_q[o0] = make_float2(f2tf(aq[0] * 0.125f), f2tf(aq[1] * 0.125f));
            *(float2*)&g_q[o1] = make_float2(f2tf(aq[2] * 0.125f), f2tf(aq[3] * 0.125f));
            *(float2*)&g_v[o0] = make_float2(f2tf(av[0]), f2tf(av[1]));
            *(float2*)&g_v[o1] = make_float2(f2tf(av[2]), f2tf(av[3]));
        }
}

// ---------------------------------------------------------------------------
// Flash attention (causal), tf32 mma. Q-tile 128, K-tile 64, 4 warps.
// Warp w: rows 32w..32w+31 (two m16 tiles) -> every B-fragment feeds 2 mmas.
// GEMM2 runs in two k-halves; P halves staged in the (dead) ks region with an
// XOR swizzle, conflict-free for both store and A-fragment load patterns.
// smem 69KB: qs [128][68], ks [64][68] (=pst [32][136]), vs [64][72].
// ---------------------------------------------------------------------------
#define ATT_SMEM ((128*68 + 64*68 + 64*72) * (int)sizeof(float))
#define PADDR(cl, r) ((cl) * 136 + ((r) ^ (((cl) & 1) << 4)))

__global__ __launch_bounds__(128, 3) void attn_kernel(float* __restrict__ out)
{
    extern __shared__ __align__(16) float sm[];
    float* qs = sm;                        // [128][68]
    float* ks = sm + 128 * 68;             // [64][68]; reused as pst
    float* vs = sm + 128 * 68 + 64 * 68;   // [64][72]

    const int tid  = threadIdx.x;
    const int lane = tid & 31;
    const int w    = tid >> 5;
    const int q4   = lane >> 2;            // 0..7
    const int c4   = lane & 3;             // 0..3
    const int qt   = (gridDim.x - 1) - blockIdx.x;   // heavy tiles first
    const int b    = blockIdx.y;
    const int qrow0 = qt * 128;
    const size_t base = (size_t)b * SEQ * HDIM;

    // load q tile 128x64
#pragma unroll
    for (int t = 0; t < 16; t++) {
        int fidx = tid + t * 128;            // 0..2047
        int r = fidx >> 4, h4 = (fidx & 15) * 4;
        *(float4*)&qs[r * 68 + h4] =
            *(const float4*)&g_q[base + (size_t)(qrow0 + r) * HDIM + h4];
    }

    float o[2][8][4];
    float m[2][2], l[2][2];
#pragma unroll
    for (int mt = 0; mt < 2; mt++) {
        m[mt][0] = -CUDART_INF_F; m[mt][1] = -CUDART_INF_F;
        l[mt][0] = 0.f; l[mt][1] = 0.f;
#pragma unroll
        for (int nt = 0; nt < 8; nt++)
#pragma unroll
            for (int e = 0; e < 4; e++) o[mt][nt][e] = 0.f;
    }

    const int rw0 = 32 * w + q4;             // mt0 row-lo (local)
    const int nkt = 2 * qt + 2;

    for (int kt = 0; kt < nkt; kt++) {
        __syncthreads();   // prior GEMM2 pst/vs reads drained before overwrite
#pragma unroll
        for (int t = 0; t < 8; t++) {
            int fidx = tid + t * 128;
            int r = fidx >> 4, h4 = (fidx & 15) * 4;
            *(float4*)&ks[r * 68 + h4] =
                *(const float4*)&g_k[base + (size_t)(kt * 64 + r) * HDIM + h4];
            *(float4*)&vs[r * 72 + h4] =
                *(const float4*)&g_v[base + (size_t)(kt * 64 + r) * HDIM + h4];
        }
        __syncthreads();

        // GEMM1: S = q @ k^T   (B-fragments shared across the 2 m16 tiles)
        float s[2][8][4];
#pragma unroll
        for (int mt = 0; mt < 2; mt++)
#pragma unroll
            for (int nt = 0; nt < 8; nt++)
#pragma unroll
                for (int e = 0; e < 4; e++) s[mt][nt][e] = 0.f;

#pragma unroll
        for (int kt8 = 0; kt8 < 8; kt8++) {
            int c = kt8 * 8 + c4;
            uint32_t a0[4], a1[4];
            a0[0] = __float_as_uint(qs[rw0 * 68 + c]);
            a0[1] = __float_as_uint(qs[(rw0 + 8) * 68 + c]);
            a0[2] = __float_as_uint(qs[rw0 * 68 + c + 4]);
            a0[3] = __float_as_uint(qs[(rw0 + 8) * 68 + c + 4]);
            a1[0] = __float_as_uint(qs[(rw0 + 16) * 68 + c]);
            a1[1] = __float_as_uint(qs[(rw0 + 24) * 68 + c]);
            a1[2] = __float_as_uint(qs[(rw0 + 16) * 68 + c + 4]);
            a1[3] = __float_as_uint(qs[(rw0 + 24) * 68 + c + 4]);
#pragma unroll
            for (int nt = 0; nt < 8; nt++) {
                int sr = nt * 8 + q4;
                uint32_t b0 = __float_as_uint(ks[sr * 68 + c]);
                uint32_t b1 = __float_as_uint(ks[sr * 68 + c + 4]);
                mma8(s[0][nt], a0, b0, b1);
                mma8(s[1][nt], a1, b0, b1);
            }
        }

        // causal mask (only the last two k-tiles touch the diagonal)
        if (kt >= 2 * qt) {
#pragma unroll
            for (int mt = 0; mt < 2; mt++) {
                int rg = 32 * w + 16 * mt + q4;           // local row within q-tile
                int cbase = (kt - 2 * qt) * 64 + 2 * c4;  // col relative to qrow0
#pragma unroll
                for (int nt = 0; nt < 8; nt++) {
                    int cg = cbase + 8 * nt;
                    if (cg     > rg)     s[mt][nt][0] = -CUDART_INF_F;
                    if (cg + 1 > rg)     s[mt][nt][1] = -CUDART_INF_F;
                    if (cg     > rg + 8) s[mt][nt][2] = -CUDART_INF_F;
                    if (cg + 1 > rg + 8) s[mt][nt][3] = -CUDART_INF_F;
                }
            }
        }

        // online softmax (4 rows per thread; quad reductions)
#pragma unroll
        for (int mt = 0; mt < 2; mt++) {
            float mx0 = -CUDART_INF_F, mx1 = -CUDART_INF_F;
#pragma unroll
            for (int nt = 0; nt < 8; nt++) {
                mx0 = fmaxf(mx0, fmaxf(s[mt][nt][0], s[mt][nt][1]));
                mx1 = fmaxf(mx1, fmaxf(s[mt][nt][2], s[mt][nt][3]));
            }
            mx0 = fmaxf(mx0, __shfl_xor_sync(0xffffffffu, mx0, 1, 4));
            mx0 = fmaxf(mx0, __shfl_xor_sync(0xffffffffu, mx0, 2, 4));
            mx1 = fmaxf(mx1, __shfl_xor_sync(0xffffffffu, mx1, 1, 4));
            mx1 = fmaxf(mx1, __shfl_xor_sync(0xffffffffu, mx1, 2, 4));

            float nm0 = fmaxf(m[mt][0], mx0), nm1 = fmaxf(m[mt][1], mx1);
            float al0 = __expf(m[mt][0] - nm0), al1 = __expf(m[mt][1] - nm1);
            m[mt][0] = nm0; m[mt][1] = nm1;

            float sum0 = 0.f, sum1 = 0.f;
#pragma unroll
            for (int nt = 0; nt < 8; nt++) {
                s[mt][nt][0] = __expf(s[mt][nt][0] - nm0); sum0 += s[mt][nt][0];
                s[mt][nt][1] = __expf(s[mt][nt][1] - nm0); sum0 += s[mt][nt][1];
                s[mt][nt][2] = __expf(s[mt][nt][2] - nm1); sum1 += s[mt][nt][2];
                s[mt][nt][3] = __expf(s[mt][nt][3] - nm1); sum1 += s[mt][nt][3];
            }
            sum0 += __shfl_xor_sync(0xffffffffu, sum0, 1, 4);
            sum0 += __shfl_xor_sync(0xffffffffu, sum0, 2, 4);
            sum1 += __shfl_xor_sync(0xffffffffu, sum1, 1, 4);
            sum1 += __shfl_xor_sync(0xffffffffu, sum1, 2, 4);
            l[mt][0] = l[mt][0] * al0 + sum0;
            l[mt][1] = l[mt][1] * al1 + sum1;
#pragma unroll
            for (int nt = 0; nt < 8; nt++) {
                o[mt][nt][0] *= al0; o[mt][nt][1] *= al0;
                o[mt][nt][2] *= al1; o[mt][nt][3] *= al1;
            }
        }

        __syncthreads();   // all warps done reading ks before it becomes pst
        float* pst = ks;

        // GEMM2 in two k-halves: stage P[:, 32*pass .. 32*pass+31] in pst
#pragma unroll
        for (int pass = 0; pass < 2; pass++) {
#pragma unroll
            for (int mt = 0; mt < 2; mt++) {
                int r0 = 32 * w + 16 * mt + q4;
#pragma unroll
                for (int ntl = 0; ntl < 4; ntl++) {
                    int nt = pass * 4 + ntl;
                    int cl0 = ntl * 8 + 2 * c4;
                    pst[PADDR(cl0,     r0)]     = f2tf(s[mt][nt][0]);
                    pst[PADDR(cl0 + 1, r0)]     = f2tf(s[mt][nt][1]);
                    pst[PADDR(cl0,     r0 + 8)] = f2tf(s[mt][nt][2]);
                    pst[PADDR(cl0 + 1, r0 + 8)] = f2tf(s[mt][nt][3]);
                }
            }
            __syncwarp();

#pragma unroll
            for (int stl = 0; stl < 4; stl++) {
                int st = pass * 4 + stl;
                int cl = stl * 8 + c4;
                uint32_t pa0[4], pa1[4];
                pa0[0] = __float_as_uint(pst[PADDR(cl,     rw0)]);
                pa0[1] = __float_as_uint(pst[PADDR(cl,     rw0 + 8)]);
                pa0[2] = __float_as_uint(pst[PADDR(cl + 4, rw0)]);
                pa0[3] = __float_as_uint(pst[PADDR(cl + 4, rw0 + 8)]);
                pa1[0] = __float_as_uint(pst[PADDR(cl,     rw0 + 16)]);
                pa1[1] = __float_as_uint(pst[PADDR(cl,     rw0 + 24)]);
                pa1[2] = __float_as_uint(pst[PADDR(cl + 4, rw0 + 16)]);
                pa1[3] = __float_as_uint(pst[PADDR(cl + 4, rw0 + 24)]);
                int vr = st * 8 + c4;
#pragma unroll
                for (int nt = 0; nt < 8; nt++) {
                    int hc = nt * 8 + q4;
                    uint32_t b0 = __float_as_uint(vs[vr * 72 + hc]);
                    uint32_t b1 = __float_as_uint(vs[(vr + 4) * 72 + hc]);
                    mma8(o[0][nt], pa0, b0, b1);
                    mma8(o[1][nt], pa1, b0, b1);
                }
            }
            __syncwarp();   // pass-0 loads done before pass-1 overwrites pst
        }
    }

    // epilogue
#pragma unroll
    for (int mt = 0; mt < 2; mt++) {
        float i0 = 1.f / l[mt][0], i1 = 1.f / l[mt][1];
        int rg = qrow0 + 32 * w + 16 * mt + q4;
#pragma unroll
        for (int nt = 0; nt < 8; nt++) {
            int cg = nt * 8 + 2 * c4;
            *(float2*)&out[base + (size_t)rg * HDIM + cg] =
                make_float2(o[mt][nt][0] * i0, o[mt][nt][1] * i0);
            *(float2*)&out[base + (size_t)(rg + 8) * HDIM + cg] =
                make_float2(o[mt][nt][2] * i1, o[mt][nt][3] * i1);
        }
    }
}

// ---------------------------------------------------------------------------
extern "C" void kernel_launch(void* const* d_in, const int* in_sizes, int n_in,
                              void* d_out, int out_size)
{
    const float* x  = (const float*)d_in[0];
    const float* Wk = (const float*)d_in[1];
    const float* Wq = (const float*)d_in[2];
    const float* Wv = (const float*)d_in[3];
    float* out = (float*)d_out;

    proj_kernel<<<M_TOT / 64, 128>>>(x, Wk, Wq, Wv);

    cudaFuncSetAttribute(attn_kernel, cudaFuncAttributeMaxDynamicSharedMemorySize,
                         ATT_SMEM);
    dim3 grid(SEQ / 128, BATCH);
    attn_kernel<<<grid, 128, ATT_SMEM>>>(out);
}

// round 7
// speedup vs baseline: 1.4210x; 1.1207x over previous
#include <cuda_runtime.h>
#include <math_constants.h>
#include <cstdint>

#define BATCH 32
#define SEQ   2048
#define CDIM  384
#define HDIM  64
#define M_TOT (BATCH*SEQ)

// q prescale: H^-0.5 * log2(e)  (softmax runs in exp2 domain)
#define QSCALE 0.180336880889761f

// scratch: q (pre-scaled, tf32-rounded), k, v — [B*T, H] row-major
__device__ __align__(16) float g_k[M_TOT*HDIM];
__device__ __align__(16) float g_q[M_TOT*HDIM];
__device__ __align__(16) float g_v[M_TOT*HDIM];

__device__ __forceinline__ float f2tf(float f) {
    uint32_t r;
    asm("cvt.rna.tf32.f32 %0, %1;" : "=r"(r) : "f"(f));
    return __uint_as_float(r);
}
__device__ __forceinline__ uint32_t f2tfu(float f) {
    uint32_t r;
    asm("cvt.rna.tf32.f32 %0, %1;" : "=r"(r) : "f"(f));
    return r;
}

// D += A@B, m16n8k8 tf32, A row-major, B col-major
__device__ __forceinline__ void mma8(float* d, const uint32_t* a, uint32_t b0, uint32_t b1) {
    asm volatile("mma.sync.aligned.m16n8k8.row.col.f32.tf32.tf32.f32 "
        "{%0,%1,%2,%3}, {%4,%5,%6,%7}, {%8,%9}, {%0,%1,%2,%3};"
        : "+f"(d[0]), "+f"(d[1]), "+f"(d[2]), "+f"(d[3])
        : "r"(a[0]), "r"(a[1]), "r"(a[2]), "r"(a[3]), "r"(b0), "r"(b1));
}

// ---------------------------------------------------------------------------
// Projection (structure = proven 89us version; only q prescale changed).
// M=65536, K=384, N=64, tf32 mma. 128 threads / 4 warps, M-tile 64.
// ---------------------------------------------------------------------------
__global__ __launch_bounds__(128) void proj_kernel(
    const float* __restrict__ x, const float* __restrict__ Wk,
    const float* __restrict__ Wq, const float* __restrict__ Wv)
{
    __shared__ __align__(16) float xs[64 * 36];      // [r][c] stride 36
    __shared__ __align__(16) float ws[3][32 * 72];   // [kc][col] stride 72

    const int tid  = threadIdx.x;
    const int lane = tid & 31;
    const int w    = tid >> 5;
    const int row0 = blockIdx.x * 64;

    float acc[3][4][2][4];
#pragma unroll
    for (int a = 0; a < 3; a++)
#pragma unroll
        for (int b = 0; b < 4; b++)
#pragma unroll
            for (int c = 0; c < 2; c++)
#pragma unroll
                for (int d = 0; d < 4; d++) acc[a][b][c][d] = 0.f;

    for (int c0 = 0; c0 < CDIM; c0 += 32) {
        __syncthreads();
#pragma unroll
        for (int t = 0; t < 4; t++) {
            int fidx = tid + t * 128;
            int r = fidx >> 3, c4 = (fidx & 7) * 4;
            float4 v = *(const float4*)&x[(size_t)(row0 + r) * CDIM + c0 + c4];
            v.x = f2tf(v.x); v.y = f2tf(v.y); v.z = f2tf(v.z); v.w = f2tf(v.w);
            *(float4*)&xs[r * 36 + c4] = v;
        }
#pragma unroll
        for (int ww = 0; ww < 3; ww++) {
            const float* W = (ww == 0) ? Wk : (ww == 1) ? Wq : Wv;
#pragma unroll
            for (int t = 0; t < 4; t++) {
                int fidx = tid + t * 128;
                int kc = fidx >> 4, col4 = (fidx & 15) * 4;
                float4 v = *(const float4*)&W[(c0 + kc) * HDIM + col4];
                v.x = f2tf(v.x); v.y = f2tf(v.y); v.z = f2tf(v.z); v.w = f2tf(v.w);
                *(float4*)&ws[ww][kc * 72 + col4] = v;
            }
        }
        __syncthreads();

#pragma unroll
        for (int kt = 0; kt < 4; kt++) {
            uint32_t a[4][4];
#pragma unroll
            for (int mt = 0; mt < 4; mt++) {
                int r = mt * 16 + (lane >> 2);
                int c = kt * 8 + (lane & 3);
                a[mt][0] = __float_as_uint(xs[r * 36 + c]);
                a[mt][1] = __float_as_uint(xs[(r + 8) * 36 + c]);
                a[mt][2] = __float_as_uint(xs[r * 36 + c + 4]);
                a[mt][3] = __float_as_uint(xs[(r + 8) * 36 + c + 4]);
            }
            int kr = kt * 8 + (lane & 3);
#pragma unroll
            for (int ww = 0; ww < 3; ww++)
#pragma unroll
                for (int ntl = 0; ntl < 2; ntl++) {
                    int n0 = (w * 2 + ntl) * 8 + (lane >> 2);
                    uint32_t b0 = __float_as_uint(ws[ww][kr * 72 + n0]);
                    uint32_t b1 = __float_as_uint(ws[ww][(kr + 4) * 72 + n0]);
#pragma unroll
                    for (int mt = 0; mt < 4; mt++)
                        mma8(acc[ww][mt][ntl], a[mt], b0, b1);
                }
        }
    }

#pragma unroll
    for (int mt = 0; mt < 4; mt++)
#pragma unroll
        for (int ntl = 0; ntl < 2; ntl++) {
            int rg = row0 + mt * 16 + (lane >> 2);
            int cg = (w * 2 + ntl) * 8 + 2 * (lane & 3);
            size_t o0 = (size_t)rg * HDIM + cg;
            size_t o1 = (size_t)(rg + 8) * HDIM + cg;
            const float* ak = acc[0][mt][ntl];
            const float* aq = acc[1][mt][ntl];
            const float* av = acc[2][mt][ntl];
            *(float2*)&g_k[o0] = make_float2(f2tf(ak[0]), f2tf(ak[1]));
            *(float2*)&g_k[o1] = make_float2(f2tf(ak[2]), f2tf(ak[3]));
            *(float2*)&g_q[o0] = make_float2(f2tf(aq[0] * QSCALE), f2tf(aq[1] * QSCALE));
            *(float2*)&g_q[o1] = make_float2(f2tf(aq[2] * QSCALE), f2tf(aq[3] * QSCALE));
            *(float2*)&g_v[o0] = make_float2(f2tf(av[0]), f2tf(av[1]));
            *(float2*)&g_v[o1] = make_float2(f2tf(av[2]), f2tf(av[3]));
        }
}

// ---------------------------------------------------------------------------
// Flash attention (causal), tf32 mma. Q-tile 64, K-tile 64, 4 warps.
// Register-resident P: V rows stored permuted (smem row j <- true row
// 2(j&3)+(j>>2) within each 8-group) so the fp32 S-accumulator fragments feed
// GEMM2's A-operand directly — no P smem round-trip, no extra syncs.
// Softmax in exp2 domain (log2e folded into q prescale).
// smem 53KB: qs [64][68], ks [64][68], vs [64][72].
// ---------------------------------------------------------------------------
#define ATT_SMEM ((64*68 + 64*68 + 64*72) * (int)sizeof(float))

__global__ __launch_bounds__(128, 3) void attn_kernel(float* __restrict__ out)
{
    extern __shared__ __align__(16) float sm[];
    float* qs = sm;                  // stride 68
    float* ks = sm + 64 * 68;        // stride 68
    float* vs = sm + 2 * 64 * 68;    // stride 72 (rows perm'd per 8-group)

    const int tid  = threadIdx.x;
    const int lane = tid & 31;
    const int w    = tid >> 5;
    const int q4   = lane >> 2;      // 0..7
    const int c4   = lane & 3;       // 0..3
    const int qt   = (gridDim.x - 1) - blockIdx.x;   // heavy tiles first
    const int b    = blockIdx.y;
    const int qrow0 = qt * 64;
    const size_t base = (size_t)b * SEQ * HDIM;

    // load q tile 64x64 (already tf32-rounded, exp2-prescaled)
#pragma unroll
    for (int t = 0; t < 8; t++) {
        int fidx = tid + t * 128;            // 0..1023
        int r = fidx >> 4, h4 = (fidx & 15) * 4;
        *(float4*)&qs[r * 68 + h4] =
            *(const float4*)&g_q[base + (size_t)(qrow0 + r) * HDIM + h4];
    }
    __syncthreads();

    // preload q fragments (A-operand) for all 8 k-steps
    uint32_t qa[8][4];
    {
        int r = w * 16 + q4;
#pragma unroll
        for (int kt8 = 0; kt8 < 8; kt8++) {
            int c = kt8 * 8 + c4;
            qa[kt8][0] = __float_as_uint(qs[r * 68 + c]);
            qa[kt8][1] = __float_as_uint(qs[(r + 8) * 68 + c]);
            qa[kt8][2] = __float_as_uint(qs[r * 68 + c + 4]);
            qa[kt8][3] = __float_as_uint(qs[(r + 8) * 68 + c + 4]);
        }
    }

    float o[8][4];
#pragma unroll
    for (int nt = 0; nt < 8; nt++)
#pragma unroll
        for (int e = 0; e < 4; e++) o[nt][e] = 0.f;
    float m0 = -CUDART_INF_F, m1 = -CUDART_INF_F, l0 = 0.f, l1 = 0.f;

    for (int kt = 0; kt <= qt; kt++) {
        __syncthreads();   // all warps done reading ks/vs from previous iter
#pragma unroll
        for (int t = 0; t < 8; t++) {
            int fidx = tid + t * 128;
            int r = fidx >> 4, h4 = (fidx & 15) * 4;
            *(float4*)&ks[r * 68 + h4] =
                *(const float4*)&g_k[base + (size_t)(kt * 64 + r) * HDIM + h4];
            // V row permutation: smem row r <- true row 2(r&3)+((r>>2)&1) in group
            int vsrc = (r & ~7) | (2 * (r & 3) + ((r >> 2) & 1));
            *(float4*)&vs[r * 72 + h4] =
                *(const float4*)&g_v[base + (size_t)(kt * 64 + vsrc) * HDIM + h4];
        }
        __syncthreads();

        // GEMM1: S = q @ k^T
        float s[8][4];
#pragma unroll
        for (int nt = 0; nt < 8; nt++)
#pragma unroll
            for (int e = 0; e < 4; e++) s[nt][e] = 0.f;

#pragma unroll
        for (int kt8 = 0; kt8 < 8; kt8++) {
            int hc = kt8 * 8 + c4;
#pragma unroll
            for (int nt = 0; nt < 8; nt++) {
                int sr = nt * 8 + q4;
                uint32_t b0 = __float_as_uint(ks[sr * 68 + hc]);
                uint32_t b1 = __float_as_uint(ks[sr * 68 + hc + 4]);
                mma8(s[nt], qa[kt8], b0, b1);
            }
        }

        // causal mask on diagonal tile
        if (kt == qt) {
            int rg = 16 * w + q4;
            int c0 = 2 * c4;
#pragma unroll
            for (int nt = 0; nt < 8; nt++) {
                int cg = c0 + 8 * nt;
                if (cg     > rg)     s[nt][0] = -CUDART_INF_F;
                if (cg + 1 > rg)     s[nt][1] = -CUDART_INF_F;
                if (cg     > rg + 8) s[nt][2] = -CUDART_INF_F;
                if (cg + 1 > rg + 8) s[nt][3] = -CUDART_INF_F;
            }
        }

        // online softmax in exp2 domain (two rows per thread; quad reductions)
        float mx0 = -CUDART_INF_F, mx1 = -CUDART_INF_F;
#pragma unroll
        for (int nt = 0; nt < 8; nt++) {
            mx0 = fmaxf(mx0, fmaxf(s[nt][0], s[nt][1]));
            mx1 = fmaxf(mx1, fmaxf(s[nt][2], s[nt][3]));
        }
        mx0 = fmaxf(mx0, __shfl_xor_sync(0xffffffffu, mx0, 1, 4));
        mx0 = fmaxf(mx0, __shfl_xor_sync(0xffffffffu, mx0, 2, 4));
        mx1 = fmaxf(mx1, __shfl_xor_sync(0xffffffffu, mx1, 1, 4));
        mx1 = fmaxf(mx1, __shfl_xor_sync(0xffffffffu, mx1, 2, 4));

        float nm0 = fmaxf(m0, mx0), nm1 = fmaxf(m1, mx1);
        float al0 = exp2f(m0 - nm0), al1 = exp2f(m1 - nm1);
        m0 = nm0; m1 = nm1;

        float sum0 = 0.f, sum1 = 0.f;
#pragma unroll
        for (int nt = 0; nt < 8; nt++) {
            s[nt][0] = exp2f(s[nt][0] - nm0); sum0 += s[nt][0];
            s[nt][1] = exp2f(s[nt][1] - nm0); sum0 += s[nt][1];
            s[nt][2] = exp2f(s[nt][2] - nm1); sum1 += s[nt][2];
            s[nt][3] = exp2f(s[nt][3] - nm1); sum1 += s[nt][3];
        }
        sum0 += __shfl_xor_sync(0xffffffffu, sum0, 1, 4);
        sum0 += __shfl_xor_sync(0xffffffffu, sum0, 2, 4);
        sum1 += __shfl_xor_sync(0xffffffffu, sum1, 1, 4);
        sum1 += __shfl_xor_sync(0xffffffffu, sum1, 2, 4);
        l0 = l0 * al0 + sum0;
        l1 = l1 * al1 + sum1;
#pragma unroll
        for (int nt = 0; nt < 8; nt++) {
            o[nt][0] *= al0; o[nt][1] *= al0;
            o[nt][2] *= al1; o[nt][3] *= al1;
        }

        // GEMM2: O += P @ V — P fragments straight from registers.
        // Accumulator layout (cols {2q,2q+1}) reinterpreted as A layout
        // (cols {q,q+4}); V rows were permuted at fill to compensate.
#pragma unroll
        for (int st = 0; st < 8; st++) {
            uint32_t pa[4];
            pa[0] = f2tfu(s[st][0]);
            pa[1] = f2tfu(s[st][2]);
            pa[2] = f2tfu(s[st][1]);
            pa[3] = f2tfu(s[st][3]);
            int vr = st * 8 + c4;
#pragma unroll
            for (int nt = 0; nt < 8; nt++) {
                int hc = nt * 8 + q4;
                uint32_t b0 = __float_as_uint(vs[vr * 72 + hc]);
                uint32_t b1 = __float_as_uint(vs[(vr + 4) * 72 + hc]);
                mma8(o[nt], pa, b0, b1);
            }
        }
    }

    // epilogue
    float i0 = 1.f / l0, i1 = 1.f / l1;
    int rg = qrow0 + 16 * w + q4;
#pragma unroll
    for (int nt = 0; nt < 8; nt++) {
        int cg = nt * 8 + 2 * c4;
        *(float2*)&out[base + (size_t)rg * HDIM + cg] =
            make_float2(o[nt][0] * i0, o[nt][1] * i0);
        *(float2*)&out[base + (size_t)(rg + 8) * HDIM + cg] =
            make_float2(o[nt][2] * i1, o[nt][3] * i1);
    }
}

// ---------------------------------------------------------------------------
extern "C" void kernel_launch(void* const* d_in, const int* in_sizes, int n_in,
                              void* d_out, int out_size)
{
    const float* x  = (const float*)d_in[0];
    const float* Wk = (const float*)d_in[1];
    const float* Wq = (const float*)d_in[2];
    const float* Wv = (const float*)d_in[3];
    float* out = (float*)d_out;

    proj_kernel<<<M_TOT / 64, 128>>>(x, Wk, Wq, Wv);

    cudaFuncSetAttribute(attn_kernel, cudaFuncAttributeMaxDynamicSharedMemorySize,
                         ATT_SMEM);
    dim3 grid(SEQ / 64, BATCH);
    attn_kernel<<<grid, 128, ATT_SMEM>>>(out);
}

// round 8
// speedup vs baseline: 1.5218x; 1.0709x over previous
#include <cuda_runtime.h>
#include <math_constants.h>
#include <cstdint>

#define BATCH 32
#define SEQ   2048
#define CDIM  384
#define HDIM  64
#define M_TOT (BATCH*SEQ)

// q prescale: H^-0.5 * log2(e)  (softmax runs in exp2 domain)
#define QSCALE 0.180336880889761f

// scratch: q (pre-scaled, tf32-rounded), k, v — [B*T, H] row-major
__device__ __align__(16) float g_k[M_TOT*HDIM];
__device__ __align__(16) float g_q[M_TOT*HDIM];
__device__ __align__(16) float g_v[M_TOT*HDIM];

__device__ __forceinline__ float f2tf(float f) {
    uint32_t r;
    asm("cvt.rna.tf32.f32 %0, %1;" : "=r"(r) : "f"(f));
    return __uint_as_float(r);
}
__device__ __forceinline__ uint32_t f2tfu(float f) {
    uint32_t r;
    asm("cvt.rna.tf32.f32 %0, %1;" : "=r"(r) : "f"(f));
    return r;
}

// D += A@B, m16n8k8 tf32, A row-major, B col-major
__device__ __forceinline__ void mma8(float* d, const uint32_t* a, uint32_t b0, uint32_t b1) {
    asm volatile("mma.sync.aligned.m16n8k8.row.col.f32.tf32.tf32.f32 "
        "{%0,%1,%2,%3}, {%4,%5,%6,%7}, {%8,%9}, {%0,%1,%2,%3};"
        : "+f"(d[0]), "+f"(d[1]), "+f"(d[2]), "+f"(d[3])
        : "r"(a[0]), "r"(a[1]), "r"(a[2]), "r"(a[3]), "r"(b0), "r"(b1));
}

__device__ __forceinline__ void cp16(uint32_t smem_dst, const float* gsrc) {
    asm volatile("cp.async.cg.shared.global [%0], [%1], 16;\n"
                 :: "r"(smem_dst), "l"(gsrc));
}

// ---------------------------------------------------------------------------
// Projection (verbatim proven 89us version; q prescale = QSCALE).
// ---------------------------------------------------------------------------
__global__ __launch_bounds__(128) void proj_kernel(
    const float* __restrict__ x, const float* __restrict__ Wk,
    const float* __restrict__ Wq, const float* __restrict__ Wv)
{
    __shared__ __align__(16) float xs[64 * 36];      // [r][c] stride 36
    __shared__ __align__(16) float ws[3][32 * 72];   // [kc][col] stride 72

    const int tid  = threadIdx.x;
    const int lane = tid & 31;
    const int w    = tid >> 5;
    const int row0 = blockIdx.x * 64;

    float acc[3][4][2][4];
#pragma unroll
    for (int a = 0; a < 3; a++)
#pragma unroll
        for (int b = 0; b < 4; b++)
#pragma unroll
            for (int c = 0; c < 2; c++)
#pragma unroll
                for (int d = 0; d < 4; d++) acc[a][b][c][d] = 0.f;

    for (int c0 = 0; c0 < CDIM; c0 += 32) {
        __syncthreads();
#pragma unroll
        for (int t = 0; t < 4; t++) {
            int fidx = tid + t * 128;
            int r = fidx >> 3, c4 = (fidx & 7) * 4;
            float4 v = *(const float4*)&x[(size_t)(row0 + r) * CDIM + c0 + c4];
            v.x = f2tf(v.x); v.y = f2tf(v.y); v.z = f2tf(v.z); v.w = f2tf(v.w);
            *(float4*)&xs[r * 36 + c4] = v;
        }
#pragma unroll
        for (int ww = 0; ww < 3; ww++) {
            const float* W = (ww == 0) ? Wk : (ww == 1) ? Wq : Wv;
#pragma unroll
            for (int t = 0; t < 4; t++) {
                int fidx = tid + t * 128;
                int kc = fidx >> 4, col4 = (fidx & 15) * 4;
                float4 v = *(const float4*)&W[(c0 + kc) * HDIM + col4];
                v.x = f2tf(v.x); v.y = f2tf(v.y); v.z = f2tf(v.z); v.w = f2tf(v.w);
                *(float4*)&ws[ww][kc * 72 + col4] = v;
            }
        }
        __syncthreads();

#pragma unroll
        for (int kt = 0; kt < 4; kt++) {
            uint32_t a[4][4];
#pragma unroll
            for (int mt = 0; mt < 4; mt++) {
                int r = mt * 16 + (lane >> 2);
                int c = kt * 8 + (lane & 3);
                a[mt][0] = __float_as_uint(xs[r * 36 + c]);
                a[mt][1] = __float_as_uint(xs[(r + 8) * 36 + c]);
                a[mt][2] = __float_as_uint(xs[r * 36 + c + 4]);
                a[mt][3] = __float_as_uint(xs[(r + 8) * 36 + c + 4]);
            }
            int kr = kt * 8 + (lane & 3);
#pragma unroll
            for (int ww = 0; ww < 3; ww++)
#pragma unroll
                for (int ntl = 0; ntl < 2; ntl++) {
                    int n0 = (w * 2 + ntl) * 8 + (lane >> 2);
                    uint32_t b0 = __float_as_uint(ws[ww][kr * 72 + n0]);
                    uint32_t b1 = __float_as_uint(ws[ww][(kr + 4) * 72 + n0]);
#pragma unroll
                    for (int mt = 0; mt < 4; mt++)
                        mma8(acc[ww][mt][ntl], a[mt], b0, b1);
                }
        }
    }

#pragma unroll
    for (int mt = 0; mt < 4; mt++)
#pragma unroll
        for (int ntl = 0; ntl < 2; ntl++) {
            int rg = row0 + mt * 16 + (lane >> 2);
            int cg = (w * 2 + ntl) * 8 + 2 * (lane & 3);
            size_t o0 = (size_t)rg * HDIM + cg;
            size_t o1 = (size_t)(rg + 8) * HDIM + cg;
            const float* ak = acc[0][mt][ntl];
            const float* aq = acc[1][mt][ntl];
            const float* av = acc[2][mt][ntl];
            *(float2*)&g_k[o0] = make_float2(f2tf(ak[0]), f2tf(ak[1]));
            *(float2*)&g_k[o1] = make_float2(f2tf(ak[2]), f2tf(ak[3]));
            *(float2*)&g_q[o0] = make_float2(f2tf(aq[0] * QSCALE), f2tf(aq[1] * QSCALE));
            *(float2*)&g_q[o1] = make_float2(f2tf(aq[2] * QSCALE), f2tf(aq[3] * QSCALE));
            *(float2*)&g_v[o0] = make_float2(f2tf(av[0]), f2tf(av[1]));
            *(float2*)&g_v[o1] = make_float2(f2tf(av[2]), f2tf(av[3]));
        }
}

// ---------------------------------------------------------------------------
// Flash attention (causal), tf32 mma, register-resident P, exp2 softmax,
// cp.async DOUBLE-BUFFERED k/v tile pipeline (tile kt+1 in flight during
// compute of kt). Q staged once in buf1's ks region, consumed into registers.
// smem 70KB: 2 x (ks [64][68] + vs [64][72]) -> 3 CTAs/SM.
// ---------------------------------------------------------------------------
#define KS_F (64*68)
#define VS_F (64*72)
#define BUF_F (KS_F + VS_F)
#define ATT_SMEM (2 * BUF_F * (int)sizeof(float))

__global__ __launch_bounds__(128, 3) void attn_kernel(float* __restrict__ out)
{
    extern __shared__ __align__(16) float sm[];

    const int tid  = threadIdx.x;
    const int lane = tid & 31;
    const int w    = tid >> 5;
    const int q4   = lane >> 2;      // 0..7
    const int c4   = lane & 3;       // 0..3
    const int qt   = (gridDim.x - 1) - blockIdx.x;   // heavy tiles first
    const int b    = blockIdx.y;
    const int qrow0 = qt * 64;
    const size_t base = (size_t)b * SEQ * HDIM;

    // stage q tile 64x64 in buf1's ks region (plain copy), preload qa, then free
    {
        float* qstage = sm + BUF_F;
#pragma unroll
        for (int t = 0; t < 8; t++) {
            int fidx = tid + t * 128;
            int r = fidx >> 4, h4 = (fidx & 15) * 4;
            *(float4*)&qstage[r * 68 + h4] =
                *(const float4*)&g_q[base + (size_t)(qrow0 + r) * HDIM + h4];
        }
    }
    __syncthreads();

    // issue prefetch of tile 0 into buf0 while we read q from buf1
    {
        float* ksb = sm;
        float* vsb = sm + KS_F;
#pragma unroll
        for (int t = 0; t < 8; t++) {
            int fidx = tid + t * 128;
            int r = fidx >> 4, h4 = (fidx & 15) * 4;
            cp16((uint32_t)__cvta_generic_to_shared(&ksb[r * 68 + h4]),
                 &g_k[base + (size_t)r * HDIM + h4]);
            int vsrc = (r & ~7) | (2 * (r & 3) + ((r >> 2) & 1));
            cp16((uint32_t)__cvta_generic_to_shared(&vsb[r * 72 + h4]),
                 &g_v[base + (size_t)vsrc * HDIM + h4]);
        }
        asm volatile("cp.async.commit_group;\n" ::: "memory");
    }

    uint32_t qa[8][4];
    {
        const float* qstage = sm + BUF_F;
        int r = w * 16 + q4;
#pragma unroll
        for (int kt8 = 0; kt8 < 8; kt8++) {
            int c = kt8 * 8 + c4;
            qa[kt8][0] = __float_as_uint(qstage[r * 68 + c]);
            qa[kt8][1] = __float_as_uint(qstage[(r + 8) * 68 + c]);
            qa[kt8][2] = __float_as_uint(qstage[r * 68 + c + 4]);
            qa[kt8][3] = __float_as_uint(qstage[(r + 8) * 68 + c + 4]);
        }
    }
    __syncthreads();   // qa reads done before kt=0 prefetches tile 1 into buf1

    float o[8][4];
#pragma unroll
    for (int nt = 0; nt < 8; nt++)
#pragma unroll
        for (int e = 0; e < 4; e++) o[nt][e] = 0.f;
    float m0 = -CUDART_INF_F, m1 = -CUDART_INF_F, l0 = 0.f, l1 = 0.f;

    for (int kt = 0; kt <= qt; kt++) {
        const int cur = kt & 1;
        float* ks = sm + cur * BUF_F;
        float* vs = ks + KS_F;

        // prefetch next tile into the other buffer; wait for current
        if (kt < qt) {
            float* ksn = sm + (1 - cur) * BUF_F;
            float* vsn = ksn + KS_F;
            const int ktn = kt + 1;
#pragma unroll
            for (int t = 0; t < 8; t++) {
                int fidx = tid + t * 128;
                int r = fidx >> 4, h4 = (fidx & 15) * 4;
                cp16((uint32_t)__cvta_generic_to_shared(&ksn[r * 68 + h4]),
                     &g_k[base + (size_t)(ktn * 64 + r) * HDIM + h4]);
                int vsrc = (r & ~7) | (2 * (r & 3) + ((r >> 2) & 1));
                cp16((uint32_t)__cvta_generic_to_shared(&vsn[r * 72 + h4]),
                     &g_v[base + (size_t)(ktn * 64 + vsrc) * HDIM + h4]);
            }
            asm volatile("cp.async.commit_group;\n" ::: "memory");
            asm volatile("cp.async.wait_group 1;\n" ::: "memory");
        } else {
            asm volatile("cp.async.wait_group 0;\n" ::: "memory");
        }
        __syncthreads();

        // GEMM1: S = q @ k^T
        float s[8][4];
#pragma unroll
        for (int nt = 0; nt < 8; nt++)
#pragma unroll
            for (int e = 0; e < 4; e++) s[nt][e] = 0.f;

#pragma unroll
        for (int kt8 = 0; kt8 < 8; kt8++) {
            int hc = kt8 * 8 + c4;
#pragma unroll
            for (int nt = 0; nt < 8; nt++) {
                int sr = nt * 8 + q4;
                uint32_t b0 = __float_as_uint(ks[sr * 68 + hc]);
                uint32_t b1 = __float_as_uint(ks[sr * 68 + hc + 4]);
                mma8(s[nt], qa[kt8], b0, b1);
            }
        }

        // causal mask on diagonal tile
        if (kt == qt) {
            int rg = 16 * w + q4;
            int c0 = 2 * c4;
#pragma unroll
            for (int nt = 0; nt < 8; nt++) {
                int cg = c0 + 8 * nt;
                if (cg     > rg)     s[nt][0] = -CUDART_INF_F;
                if (cg + 1 > rg)     s[nt][1] = -CUDART_INF_F;
                if (cg     > rg + 8) s[nt][2] = -CUDART_INF_F;
                if (cg + 1 > rg + 8) s[nt][3] = -CUDART_INF_F;
            }
        }

        // online softmax in exp2 domain (two rows per thread; quad reductions)
        float mx0 = -CUDART_INF_F, mx1 = -CUDART_INF_F;
#pragma unroll
        for (int nt = 0; nt < 8; nt++) {
            mx0 = fmaxf(mx0, fmaxf(s[nt][0], s[nt][1]));
            mx1 = fmaxf(mx1, fmaxf(s[nt][2], s[nt][3]));
        }
        mx0 = fmaxf(mx0, __shfl_xor_sync(0xffffffffu, mx0, 1, 4));
        mx0 = fmaxf(mx0, __shfl_xor_sync(0xffffffffu, mx0, 2, 4));
        mx1 = fmaxf(mx1, __shfl_xor_sync(0xffffffffu, mx1, 1, 4));
        mx1 = fmaxf(mx1, __shfl_xor_sync(0xffffffffu, mx1, 2, 4));

        float nm0 = fmaxf(m0, mx0), nm1 = fmaxf(m1, mx1);
        float al0 = exp2f(m0 - nm0), al1 = exp2f(m1 - nm1);
        m0 = nm0; m1 = nm1;

        float sum0 = 0.f, sum1 = 0.f;
#pragma unroll
        for (int nt = 0; nt < 8; nt++) {
            s[nt][0] = exp2f(s[nt][0] - nm0); sum0 += s[nt][0];
            s[nt][1] = exp2f(s[nt][1] - nm0); sum0 += s[nt][1];
            s[nt][2] = exp2f(s[nt][2] - nm1); sum1 += s[nt][2];
            s[nt][3] = exp2f(s[nt][3] - nm1); sum1 += s[nt][3];
        }
        sum0 += __shfl_xor_sync(0xffffffffu, sum0, 1, 4);
        sum0 += __shfl_xor_sync(0xffffffffu, sum0, 2, 4);
        sum1 += __shfl_xor_sync(0xffffffffu, sum1, 1, 4);
        sum1 += __shfl_xor_sync(0xffffffffu, sum1, 2, 4);
        l0 = l0 * al0 + sum0;
        l1 = l1 * al1 + sum1;
#pragma unroll
        for (int nt = 0; nt < 8; nt++) {
            o[nt][0] *= al0; o[nt][1] *= al0;
            o[nt][2] *= al1; o[nt][3] *= al1;
        }

        // GEMM2: O += P @ V — P fragments straight from registers
        // (V rows permuted at fill to match the accumulator layout).
#pragma unroll
        for (int st = 0; st < 8; st++) {
            uint32_t pa[4];
            pa[0] = f2tfu(s[st][0]);
            pa[1] = f2tfu(s[st][2]);
            pa[2] = f2tfu(s[st][1]);
            pa[3] = f2tfu(s[st][3]);
            int vr = st * 8 + c4;
#pragma unroll
            for (int nt = 0; nt < 8; nt++) {
                int hc = nt * 8 + q4;
                uint32_t b0 = __float_as_uint(vs[vr * 72 + hc]);
                uint32_t b1 = __float_as_uint(vs[(vr + 4) * 72 + hc]);
                mma8(o[nt], pa, b0, b1);
            }
        }
        __syncthreads();   // buf[cur] free before iter kt+1 prefetches into it
    }

    // epilogue
    float i0 = 1.f / l0, i1 = 1.f / l1;
    int rg = qrow0 + 16 * w + q4;
#pragma unroll
    for (int nt = 0; nt < 8; nt++) {
        int cg = nt * 8 + 2 * c4;
        *(float2*)&out[base + (size_t)rg * HDIM + cg] =
            make_float2(o[nt][0] * i0, o[nt][1] * i0);
        *(float2*)&out[base + (size_t)(rg + 8) * HDIM + cg] =
            make_float2(o[nt][2] * i1, o[nt][3] * i1);
    }
}

// ---------------------------------------------------------------------------
extern "C" void kernel_launch(void* const* d_in, const int* in_sizes, int n_in,
                              void* d_out, int out_size)
{
    const float* x  = (const float*)d_in[0];
    const float* Wk = (const float*)d_in[1];
    const float* Wq = (const float*)d_in[2];
    const float* Wv = (const float*)d_in[3];
    float* out = (float*)d_out;

    proj_kernel<<<M_TOT / 64, 128>>>(x, Wk, Wq, Wv);

    cudaFuncSetAttribute(attn_kernel, cudaFuncAttributeMaxDynamicSharedMemorySize,
                         ATT_SMEM);
    dim3 grid(SEQ / 64, BATCH);
    attn_kernel<<<grid, 128, ATT_SMEM>>>(out);
}

// round 9
// speedup vs baseline: 1.5264x; 1.0030x over previous
#include <cuda_runtime.h>
#include <math_constants.h>
#include <cstdint>

#define BATCH 32
#define SEQ   2048
#define CDIM  384
#define HDIM  64
#define M_TOT (BATCH*SEQ)

// q prescale: H^-0.5 * log2(e)  (softmax runs in exp2 domain)
#define QSCALE 0.180336880889761f

// scratch (tf32-rounded):
//   g_k, g_q : [B*T][h]
//   g_vt     : [b*64+h][T], with s-permutation ((s&7)>>1)|((s&1)<<2) baked
//              into the low 3 bits of T (matches register-P GEMM2 layout)
__device__ __align__(16) float g_k [M_TOT*HDIM];
__device__ __align__(16) float g_q [M_TOT*HDIM];
__device__ __align__(16) float g_vt[M_TOT*HDIM];

__device__ __forceinline__ float f2tf(float f) {
    uint32_t r;
    asm("cvt.rna.tf32.f32 %0, %1;" : "=r"(r) : "f"(f));
    return __uint_as_float(r);
}
__device__ __forceinline__ uint32_t f2tfu(float f) {
    uint32_t r;
    asm("cvt.rna.tf32.f32 %0, %1;" : "=r"(r) : "f"(f));
    return r;
}

// D += A@B, m16n8k8 tf32, A row-major, B col-major
__device__ __forceinline__ void mma8(float* d, const uint32_t* a, uint32_t b0, uint32_t b1) {
    asm volatile("mma.sync.aligned.m16n8k8.row.col.f32.tf32.tf32.f32 "
        "{%0,%1,%2,%3}, {%4,%5,%6,%7}, {%8,%9}, {%0,%1,%2,%3};"
        : "+f"(d[0]), "+f"(d[1]), "+f"(d[2]), "+f"(d[3])
        : "r"(a[0]), "r"(a[1]), "r"(a[2]), "r"(a[3]), "r"(b0), "r"(b1));
}

__device__ __forceinline__ void ldsm4(uint32_t& r0, uint32_t& r1, uint32_t& r2,
                                      uint32_t& r3, uint32_t addr) {
    asm volatile("ldmatrix.sync.aligned.m8n8.x4.shared.b16 {%0,%1,%2,%3}, [%4];"
        : "=r"(r0), "=r"(r1), "=r"(r2), "=r"(r3) : "r"(addr));
}

__device__ __forceinline__ void cp16(uint32_t smem_dst, const float* gsrc) {
    asm volatile("cp.async.cg.shared.global [%0], [%1], 16;\n"
                 :: "r"(smem_dst), "l"(gsrc));
}

// ---------------------------------------------------------------------------
// Projection (proven structure; v written to g_vt transposed + s-permuted).
// ---------------------------------------------------------------------------
__global__ __launch_bounds__(128) void proj_kernel(
    const float* __restrict__ x, const float* __restrict__ Wk,
    const float* __restrict__ Wq, const float* __restrict__ Wv)
{
    __shared__ __align__(16) float xs[64 * 36];      // [r][c] stride 36
    __shared__ __align__(16) float ws[3][32 * 72];   // [kc][col] stride 72

    const int tid  = threadIdx.x;
    const int lane = tid & 31;
    const int w    = tid >> 5;
    const int row0 = blockIdx.x * 64;

    float acc[3][4][2][4];
#pragma unroll
    for (int a = 0; a < 3; a++)
#pragma unroll
        for (int b = 0; b < 4; b++)
#pragma unroll
            for (int c = 0; c < 2; c++)
#pragma unroll
                for (int d = 0; d < 4; d++) acc[a][b][c][d] = 0.f;

    for (int c0 = 0; c0 < CDIM; c0 += 32) {
        __syncthreads();
#pragma unroll
        for (int t = 0; t < 4; t++) {
            int fidx = tid + t * 128;
            int r = fidx >> 3, c4 = (fidx & 7) * 4;
            float4 v = *(const float4*)&x[(size_t)(row0 + r) * CDIM + c0 + c4];
            v.x = f2tf(v.x); v.y = f2tf(v.y); v.z = f2tf(v.z); v.w = f2tf(v.w);
            *(float4*)&xs[r * 36 + c4] = v;
        }
#pragma unroll
        for (int ww = 0; ww < 3; ww++) {
            const float* W = (ww == 0) ? Wk : (ww == 1) ? Wq : Wv;
#pragma unroll
            for (int t = 0; t < 4; t++) {
                int fidx = tid + t * 128;
                int kc = fidx >> 4, col4 = (fidx & 15) * 4;
                float4 v = *(const float4*)&W[(c0 + kc) * HDIM + col4];
                v.x = f2tf(v.x); v.y = f2tf(v.y); v.z = f2tf(v.z); v.w = f2tf(v.w);
                *(float4*)&ws[ww][kc * 72 + col4] = v;
            }
        }
        __syncthreads();

#pragma unroll
        for (int kt = 0; kt < 4; kt++) {
            uint32_t a[4][4];
#pragma unroll
            for (int mt = 0; mt < 4; mt++) {
                int r = mt * 16 + (lane >> 2);
                int c = kt * 8 + (lane & 3);
                a[mt][0] = __float_as_uint(xs[r * 36 + c]);
                a[mt][1] = __float_as_uint(xs[(r + 8) * 36 + c]);
                a[mt][2] = __float_as_uint(xs[r * 36 + c + 4]);
                a[mt][3] = __float_as_uint(xs[(r + 8) * 36 + c + 4]);
            }
            int kr = kt * 8 + (lane & 3);
#pragma unroll
            for (int ww = 0; ww < 3; ww++)
#pragma unroll
                for (int ntl = 0; ntl < 2; ntl++) {
                    int n0 = (w * 2 + ntl) * 8 + (lane >> 2);
                    uint32_t b0 = __float_as_uint(ws[ww][kr * 72 + n0]);
                    uint32_t b1 = __float_as_uint(ws[ww][(kr + 4) * 72 + n0]);
#pragma unroll
                    for (int mt = 0; mt < 4; mt++)
                        mma8(acc[ww][mt][ntl], a[mt], b0, b1);
                }
        }
    }

#pragma unroll
    for (int mt = 0; mt < 4; mt++)
#pragma unroll
        for (int ntl = 0; ntl < 2; ntl++) {
            int rg = row0 + mt * 16 + (lane >> 2);
            int cg = (w * 2 + ntl) * 8 + 2 * (lane & 3);
            size_t o0 = (size_t)rg * HDIM + cg;
            size_t o1 = (size_t)(rg + 8) * HDIM + cg;
            const float* ak = acc[0][mt][ntl];
            const float* aq = acc[1][mt][ntl];
            const float* av = acc[2][mt][ntl];
            *(float2*)&g_k[o0] = make_float2(f2tf(ak[0]), f2tf(ak[1]));
            *(float2*)&g_k[o1] = make_float2(f2tf(ak[2]), f2tf(ak[3]));
            *(float2*)&g_q[o0] = make_float2(f2tf(aq[0] * QSCALE), f2tf(aq[1] * QSCALE));
            *(float2*)&g_q[o1] = make_float2(f2tf(aq[2] * QSCALE), f2tf(aq[3] * QSCALE));
            // v transposed + s-permuted: g_vt[b*64+h][tperm]
            int b  = rg >> 11;
            int t0 = rg & 2047;
            int tp = (t0 & ~7) | ((t0 & 7) >> 1) | ((t0 & 1) << 2);
            size_t vb0 = (size_t)(b * 64 + cg) * SEQ;
            size_t vb1 = (size_t)(b * 64 + cg + 1) * SEQ;
            g_vt[vb0 + tp]     = f2tf(av[0]);
            g_vt[vb1 + tp]     = f2tf(av[1]);
            g_vt[vb0 + tp + 8] = f2tf(av[2]);
            g_vt[vb1 + tp + 8] = f2tf(av[3]);
        }
}

// ---------------------------------------------------------------------------
// Flash attention (causal), tf32 mma, register-resident P, exp2 softmax,
// cp.async double buffering, ldmatrix B-fragments (4 fragments/instr).
// smem 72KB: 2 x (ks [64][68] + vst [64][76]) -> 3 CTAs/SM.
// ---------------------------------------------------------------------------
#define KS_F (64*68)
#define VS_F (64*76)
#define BUF_F (KS_F + VS_F)
#define ATT_SMEM (2 * BUF_F * (int)sizeof(float))

__global__ __launch_bounds__(128, 3) void attn_kernel(float* __restrict__ out)
{
    extern __shared__ __align__(16) float sm[];

    const int tid  = threadIdx.x;
    const int lane = tid & 31;
    const int w    = tid >> 5;
    const int q4   = lane >> 2;      // 0..7
    const int c4   = lane & 3;       // 0..3
    const int qt   = (gridDim.x - 1) - blockIdx.x;   // heavy tiles first
    const int b    = blockIdx.y;
    const int qrow0 = qt * 64;
    const size_t base = (size_t)b * SEQ * HDIM;
    const size_t vtbase = (size_t)b * 64 * SEQ;

    // ldmatrix lane offsets (element units): matrix sel = lane>>3
    //   row-within-matrix = lane&7; msel bit1 -> +8 rows; bit0 -> +4 k-cols
    const int lmrow = ((lane >> 4) & 1) * 8 + (lane & 7);
    const int lmcol = ((lane >> 3) & 1) * 4;
    const int lmoff_ks = lmrow * 68 + lmcol;
    const int lmoff_vs = lmrow * 76 + lmcol;

    // stage q tile in buf1's ks region, preload qa, then free
    {
        float* qstage = sm + BUF_F;
#pragma unroll
        for (int t = 0; t < 8; t++) {
            int fidx = tid + t * 128;
            int r = fidx >> 4, h4 = (fidx & 15) * 4;
            *(float4*)&qstage[r * 68 + h4] =
                *(const float4*)&g_q[base + (size_t)(qrow0 + r) * HDIM + h4];
        }
    }
    __syncthreads();

    // prefetch tile 0 into buf0
    {
        float* ksb = sm;
        float* vsb = sm + KS_F;
#pragma unroll
        for (int t = 0; t < 8; t++) {
            int fidx = tid + t * 128;
            int r = fidx >> 4, c16 = (fidx & 15) * 4;
            cp16((uint32_t)__cvta_generic_to_shared(&ksb[r * 68 + c16]),
                 &g_k[base + (size_t)r * HDIM + c16]);
            cp16((uint32_t)__cvta_generic_to_shared(&vsb[r * 76 + c16]),
                 &g_vt[vtbase + (size_t)r * SEQ + c16]);
        }
        asm volatile("cp.async.commit_group;\n" ::: "memory");
    }

    uint32_t qa[8][4];
    {
        const float* qstage = sm + BUF_F;
        int r = w * 16 + q4;
#pragma unroll
        for (int kt8 = 0; kt8 < 8; kt8++) {
            int c = kt8 * 8 + c4;
            qa[kt8][0] = __float_as_uint(qstage[r * 68 + c]);
            qa[kt8][1] = __float_as_uint(qstage[(r + 8) * 68 + c]);
            qa[kt8][2] = __float_as_uint(qstage[r * 68 + c + 4]);
            qa[kt8][3] = __float_as_uint(qstage[(r + 8) * 68 + c + 4]);
        }
    }
    __syncthreads();   // qa reads done before kt=0 prefetches into buf1

    float o[8][4];
#pragma unroll
    for (int nt = 0; nt < 8; nt++)
#pragma unroll
        for (int e = 0; e < 4; e++) o[nt][e] = 0.f;
    float m0 = -CUDART_INF_F, m1 = -CUDART_INF_F, l0 = 0.f, l1 = 0.f;

    for (int kt = 0; kt <= qt; kt++) {
        const int cur = kt & 1;
        float* ks = sm + cur * BUF_F;
        float* vs = ks + KS_F;
        const uint32_t ks_u = (uint32_t)__cvta_generic_to_shared(ks) + lmoff_ks * 4;
        const uint32_t vs_u = (uint32_t)__cvta_generic_to_shared(vs) + lmoff_vs * 4;

        // prefetch next tile into the other buffer; wait for current
        if (kt < qt) {
            float* ksn = sm + (1 - cur) * BUF_F;
            float* vsn = ksn + KS_F;
            const int ktn = kt + 1;
#pragma unroll
            for (int t = 0; t < 8; t++) {
                int fidx = tid + t * 128;
                int r = fidx >> 4, c16 = (fidx & 15) * 4;
                cp16((uint32_t)__cvta_generic_to_shared(&ksn[r * 68 + c16]),
                     &g_k[base + (size_t)(ktn * 64 + r) * HDIM + c16]);
                cp16((uint32_t)__cvta_generic_to_shared(&vsn[r * 76 + c16]),
                     &g_vt[vtbase + (size_t)r * SEQ + ktn * 64 + c16]);
            }
            asm volatile("cp.async.commit_group;\n" ::: "memory");
            asm volatile("cp.async.wait_group 1;\n" ::: "memory");
        } else {
            asm volatile("cp.async.wait_group 0;\n" ::: "memory");
        }
        __syncthreads();

        // GEMM1: S = q @ k^T  (B-fragments: 1 ldmatrix.x4 per 2 n-tiles)
        float s[8][4];
#pragma unroll
        for (int nt = 0; nt < 8; nt++)
#pragma unroll
            for (int e = 0; e < 4; e++) s[nt][e] = 0.f;

#pragma unroll
        for (int kt8 = 0; kt8 < 8; kt8++) {
#pragma unroll
            for (int ntp = 0; ntp < 4; ntp++) {
                uint32_t r0, r1, r2, r3;
                ldsm4(r0, r1, r2, r3, ks_u + (ntp * 16 * 68 + kt8 * 8) * 4);
                mma8(s[2 * ntp],     qa[kt8], r0, r1);
                mma8(s[2 * ntp + 1], qa[kt8], r2, r3);
            }
        }

        // causal mask on diagonal tile
        if (kt == qt) {
            int rg = 16 * w + q4;
            int c0 = 2 * c4;
#pragma unroll
            for (int nt = 0; nt < 8; nt++) {
                int cg = c0 + 8 * nt;
                if (cg     > rg)     s[nt][0] = -CUDART_INF_F;
                if (cg + 1 > rg)     s[nt][1] = -CUDART_INF_F;
                if (cg     > rg + 8) s[nt][2] = -CUDART_INF_F;
                if (cg + 1 > rg + 8) s[nt][3] = -CUDART_INF_F;
            }
        }

        // online softmax in exp2 domain
        float mx0 = -CUDART_INF_F, mx1 = -CUDART_INF_F;
#pragma unroll
        for (int nt = 0; nt < 8; nt++) {
            mx0 = fmaxf(mx0, fmaxf(s[nt][0], s[nt][1]));
            mx1 = fmaxf(mx1, fmaxf(s[nt][2], s[nt][3]));
        }
        mx0 = fmaxf(mx0, __shfl_xor_sync(0xffffffffu, mx0, 1, 4));
        mx0 = fmaxf(mx0, __shfl_xor_sync(0xffffffffu, mx0, 2, 4));
        mx1 = fmaxf(mx1, __shfl_xor_sync(0xffffffffu, mx1, 1, 4));
        mx1 = fmaxf(mx1, __shfl_xor_sync(0xffffffffu, mx1, 2, 4));

        float nm0 = fmaxf(m0, mx0), nm1 = fmaxf(m1, mx1);
        float al0 = exp2f(m0 - nm0), al1 = exp2f(m1 - nm1);
        m0 = nm0; m1 = nm1;

        float sum0 = 0.f, sum1 = 0.f;
#pragma unroll
        for (int nt = 0; nt < 8; nt++) {
            s[nt][0] = exp2f(s[nt][0] - nm0); sum0 += s[nt][0];
            s[nt][1] = exp2f(s[nt][1] - nm0); sum0 += s[nt][1];
            s[nt][2] = exp2f(s[nt][2] - nm1); sum1 += s[nt][2];
            s[nt][3] = exp2f(s[nt][3] - nm1); sum1 += s[nt][3];
        }
        sum0 += __shfl_xor_sync(0xffffffffu, sum0, 1, 4);
        sum0 += __shfl_xor_sync(0xffffffffu, sum0, 2, 4);
        sum1 += __shfl_xor_sync(0xffffffffu, sum1, 1, 4);
        sum1 += __shfl_xor_sync(0xffffffffu, sum1, 2, 4);
        l0 = l0 * al0 + sum0;
        l1 = l1 * al1 + sum1;
#pragma unroll
        for (int nt = 0; nt < 8; nt++) {
            o[nt][0] *= al0; o[nt][1] *= al0;
            o[nt][2] *= al1; o[nt][3] *= al1;
        }

        // GEMM2: O += P @ V — P from registers, V via ldmatrix (s-perm baked)
#pragma unroll
        for (int st = 0; st < 8; st++) {
            uint32_t pa[4];
            pa[0] = f2tfu(s[st][0]);
            pa[1] = f2tfu(s[st][2]);
            pa[2] = f2tfu(s[st][1]);
            pa[3] = f2tfu(s[st][3]);
#pragma unroll
            for (int ntp = 0; ntp < 4; ntp++) {
                uint32_t r0, r1, r2, r3;
                ldsm4(r0, r1, r2, r3, vs_u + (ntp * 16 * 76 + st * 8) * 4);
                mma8(o[2 * ntp],     pa, r0, r1);
                mma8(o[2 * ntp + 1], pa, r2, r3);
            }
        }
        __syncthreads();   // buf[cur] free before iter kt+1 prefetches into it
    }

    // epilogue
    float i0 = 1.f / l0, i1 = 1.f / l1;
    int rg = qrow0 + 16 * w + q4;
#pragma unroll
    for (int nt = 0; nt < 8; nt++) {
        int cg = nt * 8 + 2 * c4;
        *(float2*)&out[base + (size_t)rg * HDIM + cg] =
            make_float2(o[nt][0] * i0, o[nt][1] * i0);
        *(float2*)&out[base + (size_t)(rg + 8) * HDIM + cg] =
            make_float2(o[nt][2] * i1, o[nt][3] * i1);
    }
}

// ---------------------------------------------------------------------------
extern "C" void kernel_launch(void* const* d_in, const int* in_sizes, int n_in,
                              void* d_out, int out_size)
{
    const float* x  = (const float*)d_in[0];
    const float* Wk = (const float*)d_in[1];
    const float* Wq = (const float*)d_in[2];
    const float* Wv = (const float*)d_in[3];
    float* out = (float*)d_out;

    proj_kernel<<<M_TOT / 64, 128>>>(x, Wk, Wq, Wv);

    cudaFuncSetAttribute(attn_kernel, cudaFuncAttributeMaxDynamicSharedMemorySize,
                         ATT_SMEM);
    dim3 grid(SEQ / 64, BATCH);
    attn_kernel<<<grid, 128, ATT_SMEM>>>(out);
}